// round 4
// baseline (speedup 1.0000x reference)
#include <cuda_runtime.h>
#include <cuda_bf16.h>
#include <math.h>

// ---------------- problem constants ----------------
#define NUM_NODES   1200000
#define NUM_PHYS    1000000
#define NUM_MOVABLE 900000
#define NBX 512
#define NBY 512
#define KW  5

// BSX = 1000/512 = 1.953125 exactly representable in f32
__device__ __constant__ float c_dummy; // keep nvcc happy if unused

static __device__ __forceinline__ float bsx_f()      { return 1.953125f; }
// (float)(BSX * sqrt(2)) computed in double then truncated to f32, matching JAX weak typing
static __device__ __forceinline__ float stretch_f()  { return (float)(1.953125 * 1.4142135623730951); }
// (float)(BSX*BSY*0.05)
static __device__ __forceinline__ float cap_f()      { return (float)(1.953125 * 1.953125 * 0.05); }
static __device__ __forceinline__ float minrate_f()  { return (float)(1.0 / 1.5); }
static __device__ __forceinline__ float maxrate_f()  { return 1.5f; }

// ---------------- scratch (no allocations allowed) ----------------
__device__ float g_pin_map[NBX * NBY];
__device__ float g_util[NBX * NBY];

// ---------------- kernels ----------------
__global__ void __launch_bounds__(256) zero_map_kernel() {
    int i = blockIdx.x * blockDim.x + threadIdx.x;
    if (i < NBX * NBY) g_pin_map[i] = 0.0f;
}

// Per-axis overlap terms, replicating the reference's clamp/mask semantics.
struct Axis {
    float ov[KW];
    int   idx[KW];
};

static __device__ __forceinline__ Axis overlap_terms(float lo, float hi) {
    Axis a;
    const float bs = bsx_f();
    int il = (int)floorf(__fdiv_rn(lo, bs));   // origin = 0
    il = max(0, min(il, NBX - 1));
#pragma unroll
    for (int k = 0; k < KW; k++) {
        int id = il + k;
        bool valid = id < NBX;
        int idc = min(id, NBX - 1);
        float blo = (float)idc * bs;           // exact
        float ov = fmaxf(fminf(hi, blo + bs) - fmaxf(lo, blo), 0.0f);
        a.ov[k]  = valid ? ov : 0.0f;
        a.idx[k] = idc;
    }
    return a;
}

__global__ void __launch_bounds__(256) scatter_kernel(
    const float* __restrict__ pos,
    const float* __restrict__ nsx,
    const float* __restrict__ nsy,
    const int*  __restrict__ pin_start)
{
    int i = blockIdx.x * blockDim.x + threadIdx.x;
    if (i >= NUM_PHYS) return;

    float sx = nsx[i];
    float sy = nsy[i];
    float hx = 0.5f * fmaxf(stretch_f(), sx);
    float hy = 0.5f * fmaxf(stretch_f(), sy);
    float cx = pos[i] + 0.5f * sx;
    float cy = pos[NUM_NODES + i] + 0.5f * sy;
    float pw = (float)(pin_start[i + 1] - pin_start[i]);
    float density = __fdiv_rn(pw, 4.0f * hx * hy);

    Axis ax = overlap_terms(cx - hx, cx + hx);
    Axis ay = overlap_terms(cy - hy, cy + hy);

#pragma unroll
    for (int kx = 0; kx < KW; kx++) {
        float ox = ax.ov[kx];
        if (ox == 0.0f) continue;
        int base = ax.idx[kx] * NBY;
#pragma unroll
        for (int ky = 0; ky < KW; ky++) {
            float c = ox * ay.ov[ky] * density;   // same op order as reference
            if (c != 0.0f) {
                atomicAdd(&g_pin_map[base + ay.idx[ky]], c);
            }
        }
    }
}

__global__ void __launch_bounds__(256) util_kernel() {
    int i = blockIdx.x * blockDim.x + threadIdx.x;
    if (i < NBX * NBY) {
        float u = __fdiv_rn(g_pin_map[i], cap_f());
        u = fminf(fmaxf(u, minrate_f()), maxrate_f());   // jnp.clip: max then min
        g_util[i] = u;
    }
}

__global__ void __launch_bounds__(256) gather_kernel(
    const float* __restrict__ pos,
    const float* __restrict__ nsx,
    const float* __restrict__ nsy,
    float* __restrict__ out)
{
    int i = blockIdx.x * blockDim.x + threadIdx.x;
    if (i >= NUM_MOVABLE) return;

    float xlo = pos[i];
    float xhi = xlo + nsx[i];
    float ylo = pos[NUM_NODES + i];
    float yhi = ylo + nsy[i];

    Axis ax = overlap_terms(xlo, xhi);
    Axis ay = overlap_terms(ylo, yhi);

    float sum = 0.0f;
#pragma unroll
    for (int kx = 0; kx < KW; kx++) {
        float wx = ax.ov[kx];
        if (wx == 0.0f) continue;
        int base = ax.idx[kx] * NBY;
#pragma unroll
        for (int ky = 0; ky < KW; ky++) {
            float w = wx * ay.ov[ky];
            if (w != 0.0f) {
                sum += w * g_util[base + ay.idx[ky]];
            }
        }
    }
    out[i] = sum;
}

// ---------------- launch ----------------
extern "C" void kernel_launch(void* const* d_in, const int* in_sizes, int n_in,
                              void* d_out, int out_size)
{
    const float* pos       = (const float*)d_in[0];   // 2*NUM_NODES
    const float* nsx       = (const float*)d_in[1];   // NUM_NODES
    const float* nsy       = (const float*)d_in[2];   // NUM_NODES
    const int*   pin_start = (const int*)  d_in[3];   // NUM_PHYS+1
    float*       out       = (float*)d_out;           // NUM_MOVABLE

    (void)in_sizes; (void)n_in; (void)out_size;

    const int T = 256;
    zero_map_kernel<<<(NBX * NBY + T - 1) / T, T>>>();
    scatter_kernel<<<(NUM_PHYS + T - 1) / T, T>>>(pos, nsx, nsy, pin_start);
    util_kernel<<<(NBX * NBY + T - 1) / T, T>>>();
    gather_kernel<<<(NUM_MOVABLE + T - 1) / T, T>>>(pos, nsx, nsy, out);
}

// round 6
// speedup vs baseline: 1.3986x; 1.3986x over previous
#include <cuda_runtime.h>
#include <cuda_bf16.h>
#include <math.h>

// ---------------- problem constants ----------------
#define NUM_NODES   1200000
#define NUM_PHYS    1000000
#define NUM_MOVABLE 900000
#define NBX 512
#define NBY 512
#define NBINS (NBX * NBY)
#define KW  5

static __device__ __forceinline__ float bsx_f()      { return 1.953125f; }
static __device__ __forceinline__ float stretch_f()  { return (float)(1.953125 * 1.4142135623730951); }
static __device__ __forceinline__ float cap_f()      { return (float)(1.953125 * 1.953125 * 0.05); }
static __device__ __forceinline__ float minrate_f()  { return (float)(1.0 / 1.5); }
static __device__ __forceinline__ float maxrate_f()  { return 1.5f; }

// ---------------- scratch (static, no allocations) ----------------
// pin map as float4 blocks for vector atomics (16B aligned)
__device__ float4 g_pin_map4[NBINS / 4];
// shifted-quad util table: g_util4[b] = (u[b], u[b+1], u[b+2], u[b+3])
__device__ float4 g_util4[NBINS];

// ---------------- helpers ----------------
struct Axis {
    float ov[KW];
    int   il;      // clamped base index
};

static __device__ __forceinline__ Axis overlap_terms(float lo, float hi) {
    Axis a;
    const float bs = bsx_f();
    int il = (int)floorf(__fdiv_rn(lo, bs));
    il = max(0, min(il, NBX - 1));
    a.il = il;
#pragma unroll
    for (int k = 0; k < KW; k++) {
        int id = il + k;
        bool valid = id < NBX;
        int idc = min(id, NBX - 1);
        float blo = (float)idc * bs;            // exact
        float ov = fmaxf(fminf(hi, blo + bs) - fmaxf(lo, blo), 0.0f);
        a.ov[k] = valid ? ov : 0.0f;
    }
    return a;
}

// ---------------- kernels ----------------
__global__ void __launch_bounds__(256) zero_map_kernel() {
    int i = blockIdx.x * blockDim.x + threadIdx.x;
    if (i < NBINS / 4) g_pin_map4[i] = make_float4(0.f, 0.f, 0.f, 0.f);
}

__global__ void __launch_bounds__(256) scatter_kernel(
    const float* __restrict__ pos,
    const float* __restrict__ nsx,
    const float* __restrict__ nsy,
    const int*  __restrict__ pin_start)
{
    int i = blockIdx.x * blockDim.x + threadIdx.x;
    if (i >= NUM_PHYS) return;

    float sx = nsx[i];
    float sy = nsy[i];
    float hx = 0.5f * fmaxf(stretch_f(), sx);
    float hy = 0.5f * fmaxf(stretch_f(), sy);
    float cx = pos[i] + 0.5f * sx;
    float cy = pos[NUM_NODES + i] + 0.5f * sy;
    float pw = (float)(pin_start[i + 1] - pin_start[i]);
    float density = __fdiv_rn(pw, 4.0f * hx * hy);

    Axis ax = overlap_terms(cx - hx, cx + hx);
    Axis ay = overlap_terms(cy - hy, cy + hy);
    // y extent = max(2.762, 2.0) < 2 bins wide -> at most 3 cells: ov[3]=ov[4]=0.
    // x extent <= 4.0 -> at most 4 rows: ov[4]=0.

    int a   = ay.il;                 // first y cell (contiguous a, a+1, a+2)
    int off = a & 3;                 // position within aligned float4 block
    int q0  = a >> 2;                // float4 block index within the row

#pragma unroll
    for (int kx = 0; kx < 4; kx++) {
        float ox = ax.ov[kx];
        if (ox == 0.0f) continue;
        int row = min(ax.il + kx, NBX - 1);      // weight 0 when invalid, but keep addr in-bounds
        float c0 = (ox * ay.ov[0]) * density;
        float c1 = (ox * ay.ov[1]) * density;
        float c2 = (ox * ay.ov[2]) * density;

        // place c0..c2 into two aligned float4 lanes starting at `off`
        float4 v0, v1;
        v0.x = (off == 0) ? c0 : 0.0f;
        v0.y = (off == 0) ? c1 : (off == 1) ? c0 : 0.0f;
        v0.z = (off == 0) ? c2 : (off == 1) ? c1 : (off == 2) ? c0 : 0.0f;
        v0.w = (off == 1) ? c2 : (off == 2) ? c1 : (off == 3) ? c0 : 0.0f;
        v1.x = (off == 2) ? c2 : (off == 3) ? c1 : 0.0f;
        v1.y = (off == 3) ? c2 : 0.0f;
        v1.z = 0.0f;
        v1.w = 0.0f;

        int qbase = row * (NBY / 4) + q0;
        if (v0.x + v0.y + v0.z + v0.w != 0.0f)   // all terms >= 0
            atomicAdd(&g_pin_map4[qbase], v0);
        if (v1.x + v1.y != 0.0f)
            atomicAdd(&g_pin_map4[qbase + 1], v1);
    }
}

__global__ void __launch_bounds__(256) util_kernel() {
    int b = blockIdx.x * blockDim.x + threadIdx.x;
    if (b >= NBINS) return;
    const float* pm = (const float*)g_pin_map4;
    float4 u;
    float* up = (float*)&u;
#pragma unroll
    for (int k = 0; k < 4; k++) {
        int j = b + k;
        float v = (j < NBINS) ? pm[j] : 0.0f;
        float r = __fdiv_rn(v, cap_f());
        r = fminf(fmaxf(r, minrate_f()), maxrate_f());
        up[k] = r;
    }
    g_util4[b] = u;
}

__global__ void __launch_bounds__(256) gather_kernel(
    const float* __restrict__ pos,
    const float* __restrict__ nsx,
    const float* __restrict__ nsy,
    float* __restrict__ out)
{
    int i = blockIdx.x * blockDim.x + threadIdx.x;
    if (i >= NUM_MOVABLE) return;

    float xlo = pos[i];
    float xhi = xlo + nsx[i];
    float ylo = pos[NUM_NODES + i];
    float yhi = ylo + nsy[i];

    Axis ax = overlap_terms(xlo, xhi);
    Axis ay = overlap_terms(ylo, yhi);
    // y extent = 2.0 -> <= 3 cells (ov[3]=ov[4]=0); x extent <= 4.0 -> <= 4 rows.

    float wy0 = ay.ov[0], wy1 = ay.ov[1], wy2 = ay.ov[2];
    int a = ay.il;

    float sum = 0.0f;
#pragma unroll
    for (int kx = 0; kx < 4; kx++) {
        float wx = ax.ov[kx];
        if (wx == 0.0f) continue;
        int row = min(ax.il + kx, NBX - 1);
        float4 u = __ldg(&g_util4[row * NBY + a]);   // u[a..a+3], one LDG.128
        sum += wx * (wy0 * u.x + wy1 * u.y + wy2 * u.z);
    }
    out[i] = sum;
}

// ---------------- launch ----------------
extern "C" void kernel_launch(void* const* d_in, const int* in_sizes, int n_in,
                              void* d_out, int out_size)
{
    const float* pos       = (const float*)d_in[0];
    const float* nsx       = (const float*)d_in[1];
    const float* nsy       = (const float*)d_in[2];
    const int*   pin_start = (const int*)  d_in[3];
    float*       out       = (float*)d_out;

    (void)in_sizes; (void)n_in; (void)out_size;

    const int T = 256;
    zero_map_kernel<<<(NBINS / 4 + T - 1) / T, T>>>();
    scatter_kernel<<<(NUM_PHYS + T - 1) / T, T>>>(pos, nsx, nsy, pin_start);
    util_kernel<<<(NBINS + T - 1) / T, T>>>();
    gather_kernel<<<(NUM_MOVABLE + T - 1) / T, T>>>(pos, nsx, nsy, out);
}

// round 7
// speedup vs baseline: 1.6554x; 1.1836x over previous
#include <cuda_runtime.h>
#include <cuda_bf16.h>
#include <math.h>

// ---------------- problem constants ----------------
#define NUM_NODES   1200000
#define NUM_PHYS    1000000
#define NUM_MOVABLE 900000
#define NBX 512
#define NBY 512
#define NBINS (NBX * NBY)
#define NQ_ROW (NBY / 4)      // 128 quads per row

static __device__ __forceinline__ float bsx_f()      { return 1.953125f; }
static __device__ __forceinline__ float stretch_f()  { return (float)(1.953125 * 1.4142135623730951); }
static __device__ __forceinline__ float cap_f()      { return (float)(1.953125 * 1.953125 * 0.05); }
static __device__ __forceinline__ float minrate_f()  { return (float)(1.0 / 1.5); }
static __device__ __forceinline__ float maxrate_f()  { return 1.5f; }

// ---------------- scratch (static, no allocations) ----------------
// Dual pin maps: A quads aligned at bin 0, B quads aligned at bin 2.
// B flat index j corresponds to bin y = j+2 within the row (j=510,511 are
// zero-only padding lanes for windows ending at y=511).
__device__ float4 g_mapA4[NBINS / 4];
__device__ float4 g_mapB4[NBINS / 4];
// shifted-quad util table: g_util4[b] = (u[b], u[b+1], u[b+2], u[b+3])
__device__ float4 g_util4[NBINS];

// ---------------- helpers ----------------
template <int KN>
static __device__ __forceinline__ int overlap_terms(float lo, float hi, float* ov) {
    const float bs = bsx_f();
    int il = (int)floorf(__fdiv_rn(lo, bs));
    il = max(0, min(il, NBX - 1));
#pragma unroll
    for (int k = 0; k < KN; k++) {
        int id = il + k;
        bool valid = id < NBX;
        int idc = min(id, NBX - 1);
        float blo = (float)idc * bs;            // exact
        float o = fmaxf(fminf(hi, blo + bs) - fmaxf(lo, blo), 0.0f);
        ov[k] = valid ? o : 0.0f;
    }
    return il;
}

// ---------------- kernels ----------------
__global__ void __launch_bounds__(256) zero_map_kernel() {
    int i = blockIdx.x * blockDim.x + threadIdx.x;
    float4 z = make_float4(0.f, 0.f, 0.f, 0.f);
    if (i < NBINS / 4) { g_mapA4[i] = z; g_mapB4[i] = z; }
}

__global__ void __launch_bounds__(256) scatter_kernel(
    const float* __restrict__ pos,
    const float* __restrict__ nsx,
    const float* __restrict__ nsy,
    const int*  __restrict__ pin_start)
{
    int i = blockIdx.x * blockDim.x + threadIdx.x;
    if (i >= NUM_PHYS) return;

    float sx = nsx[i];
    float sy = nsy[i];
    float hx = 0.5f * fmaxf(stretch_f(), sx);
    float hy = 0.5f * fmaxf(stretch_f(), sy);
    float cx = pos[i] + 0.5f * sx;
    float cy = pos[NUM_NODES + i] + 0.5f * sy;
    float pw = (float)(pin_start[i + 1] - pin_start[i]);
    float density = __fdiv_rn(pw, 4.0f * hx * hy);

    float ox[4], oy[3];
    int xil = overlap_terms<4>(cx - hx, cx + hx, ox);  // x window: <= 4 rows
    int a   = overlap_terms<3>(cy - hy, cy + hy, oy);  // y window: <= 3 cells

    int off  = a & 3;
    bool useB = off >= 2;
    int j    = useB ? (a - 2) : a;      // bin index in the chosen map's space
    int qcol = j >> 2;                   // quad column within the row
    int off2 = off & 1;                  // start position within the quad (0 or 1)
    float4* map = useB ? g_mapB4 : g_mapA4;

#pragma unroll
    for (int kx = 0; kx < 4; kx++) {
        float oxk = ox[kx];
        if (oxk == 0.0f) continue;
        int row = xil + kx;              // valid whenever oxk != 0
        float c0 = (oxk * oy[0]) * density;
        float c1 = (oxk * oy[1]) * density;
        float c2 = (oxk * oy[2]) * density;
        float4 v;
        if (off2 == 0) v = make_float4(c0, c1, c2, 0.0f);
        else           v = make_float4(0.0f, c0, c1, c2);
        atomicAdd(&map[row * NQ_ROW + qcol], v);
    }
}

__global__ void __launch_bounds__(256) util_kernel() {
    int b = blockIdx.x * blockDim.x + threadIdx.x;
    if (b >= NBINS) return;
    const float* A = (const float*)g_mapA4;
    const float* B = (const float*)g_mapB4;
    float4 u;
    float* up = (float*)&u;
#pragma unroll
    for (int k = 0; k < 4; k++) {
        int jdx = b + k;
        float v = 0.0f;
        if (jdx < NBINS) {
            int yj = jdx & (NBY - 1);
            v = A[jdx] + ((yj >= 2) ? B[jdx - 2] : 0.0f);
        }
        float r = __fdiv_rn(v, cap_f());
        r = fminf(fmaxf(r, minrate_f()), maxrate_f());
        up[k] = r;
    }
    g_util4[b] = u;
}

__global__ void __launch_bounds__(256) gather_kernel(
    const float* __restrict__ pos,
    const float* __restrict__ nsx,
    const float* __restrict__ nsy,
    float* __restrict__ out)
{
    int t = blockIdx.x * blockDim.x + threadIdx.x;
    int i0 = 2 * t;
    if (i0 >= NUM_MOVABLE) return;   // NUM_MOVABLE even -> pairs exact

    float2 px = *(const float2*)(pos + i0);
    float2 py = *(const float2*)(pos + NUM_NODES + i0);
    float2 vsx = *(const float2*)(nsx + i0);
    float2 vsy = *(const float2*)(nsy + i0);

    float ox0[4], oy0[3], ox1[4], oy1[3];
    int xil0 = overlap_terms<4>(px.x, px.x + vsx.x, ox0);
    int a0   = overlap_terms<3>(py.x, py.x + vsy.x, oy0);
    int xil1 = overlap_terms<4>(px.y, px.y + vsx.y, ox1);
    int a1   = overlap_terms<3>(py.y, py.y + vsy.y, oy1);

    float sum0 = 0.0f, sum1 = 0.0f;
#pragma unroll
    for (int kx = 0; kx < 4; kx++) {
        float wx = ox0[kx];
        if (wx != 0.0f) {
            int row = xil0 + kx;
            float4 u = __ldg(&g_util4[row * NBY + a0]);
            sum0 += wx * (oy0[0] * u.x + oy0[1] * u.y + oy0[2] * u.z);
        }
    }
#pragma unroll
    for (int kx = 0; kx < 4; kx++) {
        float wx = ox1[kx];
        if (wx != 0.0f) {
            int row = xil1 + kx;
            float4 u = __ldg(&g_util4[row * NBY + a1]);
            sum1 += wx * (oy1[0] * u.x + oy1[1] * u.y + oy1[2] * u.z);
        }
    }
    *(float2*)(out + i0) = make_float2(sum0, sum1);
}

// ---------------- launch ----------------
extern "C" void kernel_launch(void* const* d_in, const int* in_sizes, int n_in,
                              void* d_out, int out_size)
{
    const float* pos       = (const float*)d_in[0];
    const float* nsx       = (const float*)d_in[1];
    const float* nsy       = (const float*)d_in[2];
    const int*   pin_start = (const int*)  d_in[3];
    float*       out       = (float*)d_out;

    (void)in_sizes; (void)n_in; (void)out_size;

    const int T = 256;
    zero_map_kernel<<<(NBINS / 4 + T - 1) / T, T>>>();
    scatter_kernel<<<(NUM_PHYS + T - 1) / T, T>>>(pos, nsx, nsy, pin_start);
    util_kernel<<<(NBINS + T - 1) / T, T>>>();
    gather_kernel<<<((NUM_MOVABLE / 2) + T - 1) / T, T>>>(pos, nsx, nsy, out);
}